// round 2
// baseline (speedup 1.0000x reference)
#include <cuda_runtime.h>
#include <cstdint>
#include <cstddef>

#define NT 4096   // sequence length
#define DD 1024   // head dim

// 64MB scratch for the score matrix + per-row 1/sum for softmax.
__device__ float g_S[(size_t)NT * NT];
__device__ float g_linv[NT];

constexpr int BM = 128, BN = 128, BK = 16;
constexpr int TM = 8,  TN = 8;
constexpr int NTH = 256;

// ---------- packed fp32x2 helpers (Blackwell sm_100+) ----------
__device__ __forceinline__ unsigned long long f2_pack(float x, float y) {
    unsigned long long r;
    asm("mov.b64 %0, {%1, %2};" : "=l"(r)
        : "r"(__float_as_uint(x)), "r"(__float_as_uint(y)));
    return r;
}
__device__ __forceinline__ unsigned long long f2_bcast(float x) {
    unsigned long long r;
    asm("mov.b64 %0, {%1, %1};" : "=l"(r) : "r"(__float_as_uint(x)));
    return r;
}
__device__ __forceinline__ void f2_fma(unsigned long long& d,
                                       unsigned long long a,
                                       unsigned long long b) {
    asm("fma.rn.f32x2 %0, %1, %2, %0;" : "+l"(d) : "l"(a), "l"(b));
}
__device__ __forceinline__ void f2_unpack(unsigned long long v, float& x, float& y) {
    unsigned lo, hi;
    asm("mov.b64 {%0, %1}, %2;" : "=r"(lo), "=r"(hi) : "l"(v));
    x = __uint_as_float(lo);
    y = __uint_as_float(hi);
}

// ============================================================================
// GEMM 1 (NT):  S[m][n] = sum_d Q[m][d] * K[n][d]
// Both operands row-major [4096, 1024]; contiguous along the K-dim.
// ============================================================================
__global__ __launch_bounds__(NTH) void qk_gemm(const float* __restrict__ A,
                                               const float* __restrict__ B)
{
    __shared__ float As[BK][BM + 4];
    __shared__ float Bs[BK][BN + 4];

    const int tid = threadIdx.x;
    const int m0 = blockIdx.y * BM;
    const int n0 = blockIdx.x * BN;

    // global-load mapping: 128 rows x 16 cols per tile, float4 per access,
    // each thread covers rows (lr, lr+64), cols lc..lc+3
    const int lr = tid >> 2;           // 0..63
    const int lc = (tid & 3) << 2;     // 0,4,8,12

    const float* Ap = A + (size_t)(m0 + lr) * DD + lc;
    const float* Bp = B + (size_t)(n0 + lr) * DD + lc;

    const int ty = tid >> 4, tx = tid & 15;
    const int tm = ty * TM, tn = tx * TN;

    unsigned long long acc[TM][TN / 2];
    #pragma unroll
    for (int i = 0; i < TM; i++)
        #pragma unroll
        for (int j = 0; j < TN / 2; j++) acc[i][j] = 0ull;

    float4 ra0, ra1, rb0, rb1;

    // prologue: prefetch tile 0
    ra0 = *reinterpret_cast<const float4*>(Ap);
    ra1 = *reinterpret_cast<const float4*>(Ap + (size_t)64 * DD);
    rb0 = *reinterpret_cast<const float4*>(Bp);
    rb1 = *reinterpret_cast<const float4*>(Bp + (size_t)64 * DD);

    As[lc + 0][lr] = ra0.x; As[lc + 1][lr] = ra0.y; As[lc + 2][lr] = ra0.z; As[lc + 3][lr] = ra0.w;
    As[lc + 0][lr + 64] = ra1.x; As[lc + 1][lr + 64] = ra1.y; As[lc + 2][lr + 64] = ra1.z; As[lc + 3][lr + 64] = ra1.w;
    Bs[lc + 0][lr] = rb0.x; Bs[lc + 1][lr] = rb0.y; Bs[lc + 2][lr] = rb0.z; Bs[lc + 3][lr] = rb0.w;
    Bs[lc + 0][lr + 64] = rb1.x; Bs[lc + 1][lr + 64] = rb1.y; Bs[lc + 2][lr + 64] = rb1.z; Bs[lc + 3][lr + 64] = rb1.w;

    for (int k0 = BK; k0 <= DD; k0 += BK) {
        __syncthreads();
        const bool more = (k0 < DD);
        if (more) {
            ra0 = *reinterpret_cast<const float4*>(Ap + k0);
            ra1 = *reinterpret_cast<const float4*>(Ap + (size_t)64 * DD + k0);
            rb0 = *reinterpret_cast<const float4*>(Bp + k0);
            rb1 = *reinterpret_cast<const float4*>(Bp + (size_t)64 * DD + k0);
        }
        #pragma unroll
        for (int kk = 0; kk < BK; kk++) {
            float4 a0 = *reinterpret_cast<const float4*>(&As[kk][tm]);
            float4 a1 = *reinterpret_cast<const float4*>(&As[kk][tm + 4]);
            float4 b0 = *reinterpret_cast<const float4*>(&Bs[kk][tn]);
            float4 b1 = *reinterpret_cast<const float4*>(&Bs[kk][tn + 4]);
            unsigned long long bp[4];
            bp[0] = f2_pack(b0.x, b0.y); bp[1] = f2_pack(b0.z, b0.w);
            bp[2] = f2_pack(b1.x, b1.y); bp[3] = f2_pack(b1.z, b1.w);
            float av[8] = {a0.x, a0.y, a0.z, a0.w, a1.x, a1.y, a1.z, a1.w};
            #pragma unroll
            for (int i = 0; i < TM; i++) {
                unsigned long long ab = f2_bcast(av[i]);
                #pragma unroll
                for (int j = 0; j < TN / 2; j++) f2_fma(acc[i][j], ab, bp[j]);
            }
        }
        __syncthreads();
        if (more) {
            As[lc + 0][lr] = ra0.x; As[lc + 1][lr] = ra0.y; As[lc + 2][lr] = ra0.z; As[lc + 3][lr] = ra0.w;
            As[lc + 0][lr + 64] = ra1.x; As[lc + 1][lr + 64] = ra1.y; As[lc + 2][lr + 64] = ra1.z; As[lc + 3][lr + 64] = ra1.w;
            Bs[lc + 0][lr] = rb0.x; Bs[lc + 1][lr] = rb0.y; Bs[lc + 2][lr] = rb0.z; Bs[lc + 3][lr] = rb0.w;
            Bs[lc + 0][lr + 64] = rb1.x; Bs[lc + 1][lr + 64] = rb1.y; Bs[lc + 2][lr + 64] = rb1.z; Bs[lc + 3][lr + 64] = rb1.w;
        }
    }

    // epilogue: vectorized stores (8 cols per row -> 2x STG.128)
    #pragma unroll
    for (int i = 0; i < TM; i++) {
        float* crow = g_S + (size_t)(m0 + tm + i) * NT + n0 + tn;
        float x0, y0, x1, y1;
        f2_unpack(acc[i][0], x0, y0); f2_unpack(acc[i][1], x1, y1);
        *reinterpret_cast<float4*>(crow) = make_float4(x0, y0, x1, y1);
        f2_unpack(acc[i][2], x0, y0); f2_unpack(acc[i][3], x1, y1);
        *reinterpret_cast<float4*>(crow + 4) = make_float4(x0, y0, x1, y1);
    }
}

// ============================================================================
// Row softmax in-place on g_S; stores 1/rowsum in g_linv (normalization is
// folded into the PV-GEMM epilogue to save one full 64MB pass).
// One block per row, 256 threads, each row value held in registers.
// ============================================================================
__global__ __launch_bounds__(256) void softmax_k()
{
    const int row = blockIdx.x;
    const int tid = threadIdx.x;
    float4* p4 = reinterpret_cast<float4*>(g_S + (size_t)row * NT);
    __shared__ float red[8];

    float4 v[4];
    #pragma unroll
    for (int it = 0; it < 4; it++) v[it] = p4[tid + it * 256];

    float m = -3.4e38f;
    #pragma unroll
    for (int it = 0; it < 4; it++) {
        m = fmaxf(m, fmaxf(fmaxf(v[it].x, v[it].y), fmaxf(v[it].z, v[it].w)));
    }
    #pragma unroll
    for (int o = 16; o > 0; o >>= 1) m = fmaxf(m, __shfl_xor_sync(0xffffffffu, m, o));
    if ((tid & 31) == 0) red[tid >> 5] = m;
    __syncthreads();
    float M = red[0];
    #pragma unroll
    for (int i = 1; i < 8; i++) M = fmaxf(M, red[i]);
    __syncthreads();

    float s = 0.0f;
    #pragma unroll
    for (int it = 0; it < 4; it++) {
        v[it].x = __expf(v[it].x - M);
        v[it].y = __expf(v[it].y - M);
        v[it].z = __expf(v[it].z - M);
        v[it].w = __expf(v[it].w - M);
        s += (v[it].x + v[it].y) + (v[it].z + v[it].w);
        p4[tid + it * 256] = v[it];
    }
    #pragma unroll
    for (int o = 16; o > 0; o >>= 1) s += __shfl_xor_sync(0xffffffffu, s, o);
    if ((tid & 31) == 0) red[tid >> 5] = s;
    __syncthreads();
    if (tid == 0) {
        float tot = 0.0f;
        #pragma unroll
        for (int i = 0; i < 8; i++) tot += red[i];
        g_linv[row] = 1.0f / tot;
    }
}

// ============================================================================
// GEMM 2 (NN):  O[m][d] = linv[m] * sum_j P[m][j] * V[j][d]
// P = g_S row-major [4096,4096], V row-major [4096,1024].
// ============================================================================
__global__ __launch_bounds__(NTH) void pv_gemm(const float* __restrict__ B,
                                               float* __restrict__ C)
{
    __shared__ float As[BK][BM + 4];
    __shared__ float Bs[BK][BN + 4];

    const int tid = threadIdx.x;
    const int m0 = blockIdx.y * BM;
    const int n0 = blockIdx.x * BN;

    // A (=P) load mapping: as in qk_gemm but Kd = NT
    const int lr = tid >> 2;
    const int lc = (tid & 3) << 2;
    const float* Ap = g_S + (size_t)(m0 + lr) * NT + lc;

    // B (=V) load mapping: 16 rows x 128 cols, rows (br, br+8), float4 at bc
    const int br = tid >> 5;          // 0..7
    const int bc = (tid & 31) << 2;   // 0..124
    const float* Bp = B + (size_t)br * DD + n0 + bc;

    const int ty = tid >> 4, tx = tid & 15;
    const int tm = ty * TM, tn = tx * TN;

    unsigned long long acc[TM][TN / 2];
    #pragma unroll
    for (int i = 0; i < TM; i++)
        #pragma unroll
        for (int j = 0; j < TN / 2; j++) acc[i][j] = 0ull;

    float4 ra0, ra1, rb0, rb1;

    ra0 = *reinterpret_cast<const float4*>(Ap);
    ra1 = *reinterpret_cast<const float4*>(Ap + (size_t)64 * NT);
    rb0 = *reinterpret_cast<const float4*>(Bp);
    rb1 = *reinterpret_cast<const float4*>(Bp + (size_t)8 * DD);

    As[lc + 0][lr] = ra0.x; As[lc + 1][lr] = ra0.y; As[lc + 2][lr] = ra0.z; As[lc + 3][lr] = ra0.w;
    As[lc + 0][lr + 64] = ra1.x; As[lc + 1][lr + 64] = ra1.y; As[lc + 2][lr + 64] = ra1.z; As[lc + 3][lr + 64] = ra1.w;
    *reinterpret_cast<float4*>(&Bs[br][bc]) = rb0;
    *reinterpret_cast<float4*>(&Bs[br + 8][bc]) = rb1;

    for (int k0 = BK; k0 <= NT; k0 += BK) {
        __syncthreads();
        const bool more = (k0 < NT);
        if (more) {
            ra0 = *reinterpret_cast<const float4*>(Ap + k0);
            ra1 = *reinterpret_cast<const float4*>(Ap + (size_t)64 * NT + k0);
            rb0 = *reinterpret_cast<const float4*>(Bp + (size_t)k0 * DD);
            rb1 = *reinterpret_cast<const float4*>(Bp + (size_t)(k0 + 8) * DD);
        }
        #pragma unroll
        for (int kk = 0; kk < BK; kk++) {
            float4 a0 = *reinterpret_cast<const float4*>(&As[kk][tm]);
            float4 a1 = *reinterpret_cast<const float4*>(&As[kk][tm + 4]);
            float4 b0 = *reinterpret_cast<const float4*>(&Bs[kk][tn]);
            float4 b1 = *reinterpret_cast<const float4*>(&Bs[kk][tn + 4]);
            unsigned long long bp[4];
            bp[0] = f2_pack(b0.x, b0.y); bp[1] = f2_pack(b0.z, b0.w);
            bp[2] = f2_pack(b1.x, b1.y); bp[3] = f2_pack(b1.z, b1.w);
            float av[8] = {a0.x, a0.y, a0.z, a0.w, a1.x, a1.y, a1.z, a1.w};
            #pragma unroll
            for (int i = 0; i < TM; i++) {
                unsigned long long ab = f2_bcast(av[i]);
                #pragma unroll
                for (int j = 0; j < TN / 2; j++) f2_fma(acc[i][j], ab, bp[j]);
            }
        }
        __syncthreads();
        if (more) {
            As[lc + 0][lr] = ra0.x; As[lc + 1][lr] = ra0.y; As[lc + 2][lr] = ra0.z; As[lc + 3][lr] = ra0.w;
            As[lc + 0][lr + 64] = ra1.x; As[lc + 1][lr + 64] = ra1.y; As[lc + 2][lr + 64] = ra1.z; As[lc + 3][lr + 64] = ra1.w;
            *reinterpret_cast<float4*>(&Bs[br][bc]) = rb0;
            *reinterpret_cast<float4*>(&Bs[br + 8][bc]) = rb1;
        }
    }

    #pragma unroll
    for (int i = 0; i < TM; i++) {
        const float li = g_linv[m0 + tm + i];
        float* crow = C + (size_t)(m0 + tm + i) * DD + n0 + tn;
        float x0, y0, x1, y1;
        f2_unpack(acc[i][0], x0, y0); f2_unpack(acc[i][1], x1, y1);
        *reinterpret_cast<float4*>(crow) = make_float4(x0 * li, y0 * li, x1 * li, y1 * li);
        f2_unpack(acc[i][2], x0, y0); f2_unpack(acc[i][3], x1, y1);
        *reinterpret_cast<float4*>(crow + 4) = make_float4(x0 * li, y0 * li, x1 * li, y1 * li);
    }
}

// ============================================================================
// Launch
// ============================================================================
extern "C" void kernel_launch(void* const* d_in, const int* in_sizes, int n_in,
                              void* d_out, int out_size)
{
    const float* q = (const float*)d_in[0];
    const float* k = (const float*)d_in[1];
    const float* v = (const float*)d_in[2];
    float* out = (float*)d_out;

    qk_gemm<<<dim3(NT / BN, NT / BM), NTH>>>(q, k);
    softmax_k<<<NT, 256>>>();
    pv_gemm<<<dim3(DD / BN, NT / BM), NTH>>>(v, out);
}

// round 4
// speedup vs baseline: 2.8630x; 2.8630x over previous
#include <cuda_runtime.h>
#include <cuda_bf16.h>
#include <cstdint>
#include <cstddef>

#define NT 4096   // sequence length
#define DD 1024   // head dim

// ---------------- device scratch (no allocs allowed) ----------------
__device__ float         g_S [(size_t)NT * NT];    // 64 MB logits
__device__ __nv_bfloat16 g_Qh[(size_t)NT * DD];
__device__ __nv_bfloat16 g_Ql[(size_t)NT * DD];
__device__ __nv_bfloat16 g_Kh[(size_t)NT * DD];
__device__ __nv_bfloat16 g_Kl[(size_t)NT * DD];
__device__ __nv_bfloat16 g_Ph[(size_t)NT * NT];    // 32 MB
__device__ __nv_bfloat16 g_Pl[(size_t)NT * NT];    // 32 MB
__device__ __nv_bfloat16 g_Vth[(size_t)DD * NT];   // V^T hi  [1024][4096]
__device__ __nv_bfloat16 g_Vtl[(size_t)DD * NT];   // V^T lo

// ---------------- helpers ----------------
__device__ __forceinline__ uint32_t smem_u32(const void* p) {
    uint32_t a;
    asm("{ .reg .u64 t; cvta.to.shared.u64 t, %1; cvt.u32.u64 %0, t; }" : "=r"(a) : "l"(p));
    return a;
}
#define SMEM_SWZ128(b) ((b) ^ (((b) >> 3) & 0x70))

__device__ __forceinline__ void cp_async16(uint32_t dst, const void* src) {
    asm volatile("cp.async.cg.shared.global [%0], [%1], 16;" :: "r"(dst), "l"(src));
}
__device__ __forceinline__ void cp_commit() { asm volatile("cp.async.commit_group;" ::: "memory"); }
template<int N> __device__ __forceinline__ void cp_wait() {
    asm volatile("cp.async.wait_group %0;" :: "n"(N) : "memory");
}

__device__ __forceinline__ void ldsm_x4(uint32_t& r0, uint32_t& r1, uint32_t& r2, uint32_t& r3,
                                        uint32_t addr) {
    asm volatile("ldmatrix.sync.aligned.m8n8.x4.shared.b16 {%0,%1,%2,%3}, [%4];"
                 : "=r"(r0), "=r"(r1), "=r"(r2), "=r"(r3) : "r"(addr));
}

__device__ __forceinline__ void mma16816(float* d, const uint32_t* a, uint32_t b0, uint32_t b1) {
    asm volatile(
        "mma.sync.aligned.m16n8k16.row.col.f32.bf16.bf16.f32 "
        "{%0,%1,%2,%3}, {%4,%5,%6,%7}, {%8,%9}, {%0,%1,%2,%3};"
        : "+f"(d[0]), "+f"(d[1]), "+f"(d[2]), "+f"(d[3])
        : "r"(a[0]), "r"(a[1]), "r"(a[2]), "r"(a[3]), "r"(b0), "r"(b1));
}

__device__ __forceinline__ uint32_t packbf(__nv_bfloat16 a, __nv_bfloat16 b) {
    __nv_bfloat162 t; t.x = a; t.y = b;
    return *reinterpret_cast<uint32_t*>(&t);
}

// ---------------- GEMM config ----------------
constexpr int GBM = 128, GBN = 128, GBK = 64;   // K chunk = 64 bf16 = 128B row
constexpr int STAGE_BYTES = GBM * 128;          // 16 KB (A or B tile per stage)
constexpr int SM_A = 0;                          // 2 stages x 16KB
constexpr int SM_B = 2 * STAGE_BYTES;            // 2 stages x 16KB
constexpr int SMEM_NEED = SM_B + 2 * STAGE_BYTES;  // 64 KB
constexpr int SMEM_TOTAL = SMEM_NEED + 1024;

// D[m][n] = sum_k (Ah+Al)[m][k]*(Bh+Bl)[n][k]  via  Ah*Bh + Al*Bh + Ah*Bl.
// A: [Mtot, KDIM] K-major bf16, B: [Ntot, KDIM] K-major bf16, C row-major lead LDC (fp32).
template<int KDIM, int LDC>
__global__ void __launch_bounds__(256)
mma_gemm(const __nv_bfloat16* __restrict__ Ah, const __nv_bfloat16* __restrict__ Al,
         const __nv_bfloat16* __restrict__ Bh, const __nv_bfloat16* __restrict__ Bl,
         float* __restrict__ C)
{
    extern __shared__ char smem_raw[];
    const uint32_t sb = (smem_u32(smem_raw) + 1023u) & ~1023u;
    const int tid = threadIdx.x;
    const int wid = tid >> 5;
    const int lane = tid & 31;
    const int m0 = blockIdx.y * GBM;
    const int n0 = blockIdx.x * GBN;

    const int wm = wid & 3;        // 4 warp-rows of 32
    const int wn = wid >> 2;       // 2 warp-cols of 64

    constexpr int CPP = KDIM / GBK;       // chunks per phase
    constexpr int NCHUNKS = 3 * CPP;

    const __nv_bfloat16* Asrc[3] = {Ah, Al, Ah};
    const __nv_bfloat16* Bsrc[3] = {Bh, Bh, Bl};

    // cp.async mapping: 128 rows x 128B per tile, 1024 16B copies, 4/thread
    const int ldr = tid >> 1;              // 0..127 (two threads per row)
    const int ldc0 = (tid & 1) * 32;       // 0 or 32 bytes; each thread does 2x16B here + rows +? 
    // simpler mapping: idx = tid + t*256; r = idx>>3; c = (idx&7)*16
    auto load_chunk = [&](int c, int s) {
        const int ph = c / CPP;
        const int koff = (c % CPP) * GBK;
        const char* srcA = (const char*)(Asrc[ph] + (size_t)m0 * KDIM + koff);
        const char* srcB = (const char*)(Bsrc[ph] + (size_t)n0 * KDIM + koff);
        const uint32_t baseA = sb + SM_A + s * STAGE_BYTES;
        const uint32_t baseB = sb + SM_B + s * STAGE_BYTES;
        #pragma unroll
        for (int t = 0; t < 4; t++) {
            int idx = tid + t * 256;
            int r = idx >> 3;
            int cB = (idx & 7) * 16;
            cp_async16(baseA + SMEM_SWZ128(r * 128 + cB), srcA + (size_t)r * (KDIM * 2) + cB);
        }
        #pragma unroll
        for (int t = 0; t < 4; t++) {
            int idx = tid + t * 256;
            int r = idx >> 3;
            int cB = (idx & 7) * 16;
            cp_async16(baseB + SMEM_SWZ128(r * 128 + cB), srcB + (size_t)r * (KDIM * 2) + cB);
        }
    };
    (void)ldr; (void)ldc0;

    float acc[2][8][4];
    #pragma unroll
    for (int i = 0; i < 2; i++)
        #pragma unroll
        for (int j = 0; j < 8; j++)
            #pragma unroll
            for (int q = 0; q < 4; q++) acc[i][j][q] = 0.0f;

    load_chunk(0, 0); cp_commit();
    load_chunk(1, 1); cp_commit();

    // per-lane ldmatrix address components
    const int a_row = wm * 32 + (lane & 15);
    const int a_csel = (lane >> 4) << 4;                     // 0 / 16 bytes
    const int b_row = wn * 64 + (lane & 7) + ((lane >> 4) << 3);
    const int b_csel = ((lane >> 3) & 1) << 4;               // 0 / 16 bytes

    for (int c = 0; c < NCHUNKS; c++) {
        const int s = c & 1;
        cp_wait<1>();
        __syncthreads();
        const uint32_t aBase = sb + SM_A + s * STAGE_BYTES;
        const uint32_t bBase = sb + SM_B + s * STAGE_BYTES;
        #pragma unroll
        for (int ks = 0; ks < 4; ks++) {
            uint32_t afr[2][4];
            #pragma unroll
            for (int mi = 0; mi < 2; mi++) {
                uint32_t addr = aBase + SMEM_SWZ128((a_row + mi * 16) * 128 + ks * 32 + a_csel);
                ldsm_x4(afr[mi][0], afr[mi][1], afr[mi][2], afr[mi][3], addr);
            }
            #pragma unroll
            for (int ni = 0; ni < 4; ni++) {
                uint32_t b0, b1, b2, b3;
                uint32_t addr = bBase + SMEM_SWZ128((b_row + ni * 16) * 128 + ks * 32 + b_csel);
                ldsm_x4(b0, b1, b2, b3, addr);
                #pragma unroll
                for (int mi = 0; mi < 2; mi++) {
                    mma16816(acc[mi][ni * 2 + 0], afr[mi], b0, b1);
                    mma16816(acc[mi][ni * 2 + 1], afr[mi], b2, b3);
                }
            }
        }
        __syncthreads();
        if (c + 2 < NCHUNKS) { load_chunk(c + 2, s); }
        cp_commit();
    }

    // ---- epilogue ----
    const int er = lane >> 2;            // 0..7
    const int ec = (lane & 3) * 2;       // 0,2,4,6
    #pragma unroll
    for (int mi = 0; mi < 2; mi++) {
        #pragma unroll
        for (int j = 0; j < 8; j++) {
            float* base = C + (size_t)(m0 + wm * 32 + mi * 16 + er) * LDC
                            + n0 + wn * 64 + j * 8 + ec;
            *reinterpret_cast<float2*>(base) = make_float2(acc[mi][j][0], acc[mi][j][1]);
            *reinterpret_cast<float2*>(base + (size_t)8 * LDC) = make_float2(acc[mi][j][2], acc[mi][j][3]);
        }
    }
}

// ---------------- fp32 -> bf16 hi/lo split ----------------
__global__ void __launch_bounds__(256) split_kernel(const float* __restrict__ x,
                                                    __nv_bfloat16* __restrict__ hi,
                                                    __nv_bfloat16* __restrict__ lo,
                                                    int n4)
{
    int i = blockIdx.x * blockDim.x + threadIdx.x;
    if (i >= n4) return;
    float4 v = reinterpret_cast<const float4*>(x)[i];
    __nv_bfloat16 h0 = __float2bfloat16(v.x), h1 = __float2bfloat16(v.y);
    __nv_bfloat16 h2 = __float2bfloat16(v.z), h3 = __float2bfloat16(v.w);
    __nv_bfloat16 l0 = __float2bfloat16(v.x - __bfloat162float(h0));
    __nv_bfloat16 l1 = __float2bfloat16(v.y - __bfloat162float(h1));
    __nv_bfloat16 l2 = __float2bfloat16(v.z - __bfloat162float(h2));
    __nv_bfloat16 l3 = __float2bfloat16(v.w - __bfloat162float(h3));
    reinterpret_cast<uint2*>(hi)[i] = make_uint2(packbf(h0, h1), packbf(h2, h3));
    reinterpret_cast<uint2*>(lo)[i] = make_uint2(packbf(l0, l1), packbf(l2, l3));
}

// ---------------- V transpose + split:  Vt[n][k] = V[k][n] ----------------
__global__ void __launch_bounds__(256) vtrans_kernel(const float* __restrict__ v)
{
    __shared__ float tile[32][33];
    const int n0 = blockIdx.x * 32;   // over DD
    const int k0 = blockIdx.y * 32;   // over NT
    const int tx = threadIdx.x, ty = threadIdx.y;  // (32, 8)
    #pragma unroll
    for (int j = 0; j < 32; j += 8)
        tile[ty + j][tx] = v[(size_t)(k0 + ty + j) * DD + n0 + tx];
    __syncthreads();
    #pragma unroll
    for (int j = 0; j < 32; j += 8) {
        const float val = tile[tx][ty + j];
        __nv_bfloat16 h = __float2bfloat16(val);
        __nv_bfloat16 l = __float2bfloat16(val - __bfloat162float(h));
        const size_t o = (size_t)(n0 + ty + j) * NT + k0 + tx;
        g_Vth[o] = h;
        g_Vtl[o] = l;
    }
}

// ---------------- softmax + normalize + bf16 hi/lo split of P ----------------
__global__ void __launch_bounds__(256) softmax_split()
{
    const int row = blockIdx.x;
    const int tid = threadIdx.x;
    const float4* p4 = reinterpret_cast<const float4*>(g_S + (size_t)row * NT);
    __shared__ float red[8];
    __shared__ float sh_inv;

    float4 v[4];
    #pragma unroll
    for (int it = 0; it < 4; it++) v[it] = p4[tid + it * 256];

    float m = -3.4e38f;
    #pragma unroll
    for (int it = 0; it < 4; it++)
        m = fmaxf(m, fmaxf(fmaxf(v[it].x, v[it].y), fmaxf(v[it].z, v[it].w)));
    #pragma unroll
    for (int o = 16; o > 0; o >>= 1) m = fmaxf(m, __shfl_xor_sync(0xffffffffu, m, o));
    if ((tid & 31) == 0) red[tid >> 5] = m;
    __syncthreads();
    float M = red[0];
    #pragma unroll
    for (int i = 1; i < 8; i++) M = fmaxf(M, red[i]);
    __syncthreads();

    float s = 0.0f;
    #pragma unroll
    for (int it = 0; it < 4; it++) {
        v[it].x = __expf(v[it].x - M);
        v[it].y = __expf(v[it].y - M);
        v[it].z = __expf(v[it].z - M);
        v[it].w = __expf(v[it].w - M);
        s += (v[it].x + v[it].y) + (v[it].z + v[it].w);
    }
    #pragma unroll
    for (int o = 16; o > 0; o >>= 1) s += __shfl_xor_sync(0xffffffffu, s, o);
    if ((tid & 31) == 0) red[tid >> 5] = s;
    __syncthreads();
    if (tid == 0) {
        float tot = 0.0f;
        #pragma unroll
        for (int i = 0; i < 8; i++) tot += red[i];
        sh_inv = 1.0f / tot;
    }
    __syncthreads();
    const float inv = sh_inv;

    uint2* ph2 = reinterpret_cast<uint2*>(g_Ph + (size_t)row * NT);
    uint2* pl2 = reinterpret_cast<uint2*>(g_Pl + (size_t)row * NT);
    #pragma unroll
    for (int it = 0; it < 4; it++) {
        float p0 = v[it].x * inv, p1 = v[it].y * inv, p2 = v[it].z * inv, p3 = v[it].w * inv;
        __nv_bfloat16 h0 = __float2bfloat16(p0), h1 = __float2bfloat16(p1);
        __nv_bfloat16 h2 = __float2bfloat16(p2), h3 = __float2bfloat16(p3);
        __nv_bfloat16 l0 = __float2bfloat16(p0 - __bfloat162float(h0));
        __nv_bfloat16 l1 = __float2bfloat16(p1 - __bfloat162float(h1));
        __nv_bfloat16 l2 = __float2bfloat16(p2 - __bfloat162float(h2));
        __nv_bfloat16 l3 = __float2bfloat16(p3 - __bfloat162float(h3));
        const int idx = tid + it * 256;
        ph2[idx] = make_uint2(packbf(h0, h1), packbf(h2, h3));
        pl2[idx] = make_uint2(packbf(l0, l1), packbf(l2, l3));
    }
}

// ---------------- launch ----------------
extern "C" void kernel_launch(void* const* d_in, const int* in_sizes, int n_in,
                              void* d_out, int out_size)
{
    const float* q = (const float*)d_in[0];
    const float* k = (const float*)d_in[1];
    const float* v = (const float*)d_in[2];
    float* out = (float*)d_out;

    void *qh, *ql, *kh, *kl, *sp, *ph, *pl, *vth, *vtl;
    cudaGetSymbolAddress(&qh, g_Qh);  cudaGetSymbolAddress(&ql, g_Ql);
    cudaGetSymbolAddress(&kh, g_Kh);  cudaGetSymbolAddress(&kl, g_Kl);
    cudaGetSymbolAddress(&sp, g_S);
    cudaGetSymbolAddress(&ph, g_Ph);  cudaGetSymbolAddress(&pl, g_Pl);
    cudaGetSymbolAddress(&vth, g_Vth); cudaGetSymbolAddress(&vtl, g_Vtl);

    cudaFuncSetAttribute(mma_gemm<DD, NT>, cudaFuncAttributeMaxDynamicSharedMemorySize, SMEM_TOTAL);
    cudaFuncSetAttribute(mma_gemm<NT, DD>, cudaFuncAttributeMaxDynamicSharedMemorySize, SMEM_TOTAL);

    const int n4 = NT * DD / 4;
    split_kernel<<<(n4 + 255) / 256, 256>>>(q, (__nv_bfloat16*)qh, (__nv_bfloat16*)ql, n4);
    split_kernel<<<(n4 + 255) / 256, 256>>>(k, (__nv_bfloat16*)kh, (__nv_bfloat16*)kl, n4);
    vtrans_kernel<<<dim3(DD / 32, NT / 32), dim3(32, 8)>>>(v);

    // S = Q K^T  (A=[NT,DD] K-major, B=[NT,DD] K-major, C=[NT,NT])
    mma_gemm<DD, NT><<<dim3(NT / GBN, NT / GBM), 256, SMEM_TOTAL>>>(
        (const __nv_bfloat16*)qh, (const __nv_bfloat16*)ql,
        (const __nv_bfloat16*)kh, (const __nv_bfloat16*)kl, (float*)sp);

    softmax_split<<<NT, 256>>>();

    // O = P V  (A=P [NT,NT] K-major, B=Vt [DD,NT] K-major, C=[NT,DD])
    mma_gemm<NT, DD><<<dim3(DD / GBN, NT / GBM), 256, SMEM_TOTAL>>>(
        (const __nv_bfloat16*)ph, (const __nv_bfloat16*)pl,
        (const __nv_bfloat16*)vth, (const __nv_bfloat16*)vtl, out);
}